// round 1
// baseline (speedup 1.0000x reference)
#include <cuda_runtime.h>
#include <mma.h>

using namespace nvcuda;

#define ROWS      128     // tokens per CTA
#define DIN       25
#define DK        32      // padded K for GEMM1
#define DP        128
#define XN_LD     40      // 160B, multiple of 16B
#define W_LD      136     // 544B, multiple of 16B; 136 mod 32 = 8 breaks conflicts
#define NTHREADS  256

// shared layout (floats)
#define OFF_W1    0                      // 32*136  = 4352
#define OFF_W2    (OFF_W1 + DK*W_LD)     // 128*136 = 17408
#define OFF_XN    (OFF_W2 + DP*W_LD)     // 128*40  = 5120
#define OFF_H     (OFF_XN + ROWS*XN_LD)  // 128*136 = 17408
#define OFF_B1    (OFF_H  + ROWS*W_LD)   // 128
#define OFF_B2    (OFF_B1 + DP)          // 128
#define OFF_G     (OFF_B2 + DP)          // 32
#define OFF_BT    (OFF_G  + DK)          // 32
#define SMEM_FLOATS (OFF_BT + DK)
#define SMEM_BYTES  (SMEM_FLOATS * 4)

__global__ __launch_bounds__(NTHREADS, 1)
void ip_fused_kernel(const float* __restrict__ x,
                     const float* __restrict__ gamma,
                     const float* __restrict__ beta,
                     const float* __restrict__ w1,
                     const float* __restrict__ b1,
                     const float* __restrict__ w2,
                     const float* __restrict__ b2,
                     float* __restrict__ out)
{
    extern __shared__ float smem[];
    float* w1s = smem + OFF_W1;
    float* w2s = smem + OFF_W2;
    float* xns = smem + OFF_XN;
    float* hs  = smem + OFF_H;
    float* b1s = smem + OFF_B1;
    float* b2s = smem + OFF_B2;
    float* gs  = smem + OFF_G;
    float* bts = smem + OFF_BT;

    const int tid  = threadIdx.x;
    const int warp = tid >> 5;
    const long long row0 = (long long)blockIdx.x * ROWS;

    // ---- stage weights/biases into shared (TF32-rounded) ----
    for (int i = tid; i < DK * DP; i += NTHREADS) {
        int k = i >> 7, p = i & 127;
        float v = (k < DIN) ? w1[k * DP + p] : 0.0f;
        w1s[k * W_LD + p] = wmma::__float_to_tf32(v);
    }
    for (int i = tid; i < DP * DP; i += NTHREADS) {
        int k = i >> 7, q = i & 127;
        w2s[k * W_LD + q] = wmma::__float_to_tf32(w2[i]);
    }
    if (tid < DP)  { b1s[tid] = b1[tid]; b2s[tid] = b2[tid]; }
    if (tid < DK)  {
        gs[tid]  = (tid < DIN) ? gamma[tid] : 0.0f;
        bts[tid] = (tid < DIN) ? beta[tid]  : 0.0f;
    }

    // ---- coalesced x tile load into hs scratch (aliased) ----
    const float* xg = x + row0 * DIN;
    for (int i = tid; i < ROWS * DIN; i += NTHREADS) hs[i] = xg[i];
    __syncthreads();

    // ---- LayerNorm: one thread per row (stride-25 shared reads: conflict free) ----
    if (tid < ROWS) {
        const float* xr = hs + tid * DIN;
        float s = 0.0f;
        #pragma unroll
        for (int i = 0; i < DIN; i++) s += xr[i];
        float mu = s * (1.0f / DIN);
        float v = 0.0f;
        #pragma unroll
        for (int i = 0; i < DIN; i++) { float d = xr[i] - mu; v += d * d; }
        float rs = rsqrtf(v * (1.0f / DIN) + 1e-5f);
        float* xo = xns + tid * XN_LD;
        #pragma unroll
        for (int i = 0; i < DIN; i++)
            xo[i] = wmma::__float_to_tf32((xr[i] - mu) * rs * gs[i] + bts[i]);
        #pragma unroll
        for (int i = DIN; i < DK; i++) xo[i] = 0.0f;
    }
    __syncthreads();

    // ---- GEMM1: [128x32] x [32x128] TF32, each warp does 16 rows x 128 cols ----
    wmma::fragment<wmma::accumulator, 16, 16, 8, float> acc[8];
    #pragma unroll
    for (int n = 0; n < 8; n++) wmma::fill_fragment(acc[n], 0.0f);

    const int m0 = warp * 16;
    #pragma unroll
    for (int k = 0; k < 4; k++) {
        wmma::fragment<wmma::matrix_a, 16, 16, 8, wmma::precision::tf32, wmma::row_major> afr;
        wmma::load_matrix_sync(afr, xns + m0 * XN_LD + k * 8, XN_LD);
        #pragma unroll
        for (int n = 0; n < 8; n++) {
            wmma::fragment<wmma::matrix_b, 16, 16, 8, wmma::precision::tf32, wmma::row_major> bfr;
            wmma::load_matrix_sync(bfr, w1s + (k * 8) * W_LD + n * 16, W_LD);
            wmma::mma_sync(acc[n], afr, bfr, acc[n]);
        }
    }
    #pragma unroll
    for (int n = 0; n < 8; n++)
        wmma::store_matrix_sync(hs + m0 * W_LD + n * 16, acc[n], W_LD, wmma::mem_row_major);
    __syncthreads();

    // ---- bias + exact-erf GELU, re-round to TF32 in place ----
    for (int i = tid; i < ROWS * DP; i += NTHREADS) {
        int r = i >> 7, c = i & 127;
        float v = hs[r * W_LD + c] + b1s[c];
        float g = 0.5f * v * (1.0f + erff(v * 0.70710678118654752f));
        hs[r * W_LD + c] = wmma::__float_to_tf32(g);
    }
    __syncthreads();

    // ---- GEMM2: [128x128] x [128x128] TF32 ----
    #pragma unroll
    for (int n = 0; n < 8; n++) wmma::fill_fragment(acc[n], 0.0f);

    for (int k = 0; k < 16; k++) {
        wmma::fragment<wmma::matrix_a, 16, 16, 8, wmma::precision::tf32, wmma::row_major> afr;
        wmma::load_matrix_sync(afr, hs + m0 * W_LD + k * 8, W_LD);
        #pragma unroll
        for (int n = 0; n < 8; n++) {
            wmma::fragment<wmma::matrix_b, 16, 16, 8, wmma::precision::tf32, wmma::row_major> bfr;
            wmma::load_matrix_sync(bfr, w2s + (k * 8) * W_LD + n * 16, W_LD);
            wmma::mma_sync(acc[n], afr, bfr, acc[n]);
        }
    }
    __syncthreads();   // all warps done reading w2s; reuse it as output staging
    #pragma unroll
    for (int n = 0; n < 8; n++)
        wmma::store_matrix_sync(w2s + m0 * W_LD + n * 16, acc[n], W_LD, wmma::mem_row_major);
    __syncthreads();

    // ---- +b2, coalesced streaming store ----
    float* og = out + row0 * DP;
    for (int i = tid; i < ROWS * DP; i += NTHREADS) {
        int r = i >> 7, c = i & 127;
        og[i] = w2s[r * W_LD + c] + b2s[c];
    }
}

extern "C" void kernel_launch(void* const* d_in, const int* in_sizes, int n_in,
                              void* d_out, int out_size)
{
    const float* x     = (const float*)d_in[0];
    const float* gamma = (const float*)d_in[1];
    const float* beta  = (const float*)d_in[2];
    const float* w1    = (const float*)d_in[3];
    const float* b1    = (const float*)d_in[4];
    const float* w2    = (const float*)d_in[5];
    const float* b2    = (const float*)d_in[6];
    float* out = (float*)d_out;

    static bool attr_set = false;   // one-time attribute set (not a work guard)
    if (!attr_set) {
        cudaFuncSetAttribute(ip_fused_kernel,
                             cudaFuncAttributeMaxDynamicSharedMemorySize,
                             SMEM_BYTES);
        attr_set = true;
    }

    const int rows = in_sizes[0] / DIN;        // 524288
    const int grid = rows / ROWS;              // 4096
    ip_fused_kernel<<<grid, NTHREADS, SMEM_BYTES>>>(x, gamma, beta, w1, b1, w2, b2, out);
}

// round 2
// speedup vs baseline: 1.3734x; 1.3734x over previous
#include <cuda_runtime.h>
#include <mma.h>

using namespace nvcuda;

#define DIN       25
#define DK        32      // padded K for GEMM1
#define DP        128
#define ROWS      128     // tokens per CTA
#define NT        512     // 16 warps
#define W_LD      132     // 528B stride: 16B multiple, 132 mod 32 = 4 (conflict-free)
#define XN_LD     36      // 144B stride: 16B multiple, 36 mod 32 = 4

// shared layout (floats)
#define OFF_W1    0                         // 32*132  = 4224
#define OFF_W2    (OFF_W1 + DK*W_LD)        // 128*132 = 16896
#define OFF_XN    (OFF_W2 + DP*W_LD)        // 128*36  = 4608
#define OFF_H     (OFF_XN + ROWS*XN_LD)     // 128*132 = 16896 (also packed-x staging)
#define OFF_B1R   (OFF_H  + ROWS*W_LD)      // 16*132  = 2112 (b1 replicated 16 rows)
#define OFF_B2R   (OFF_B1R + 16*W_LD)       // 16*132  = 2112
#define OFF_G     (OFF_B2R + 16*W_LD)       // 32
#define OFF_BT    (OFF_G + DK)              // 32
#define SMEM_FLOATS (OFF_BT + DK)
#define SMEM_BYTES  (SMEM_FLOATS * 4)       // ~187.6 KB

__global__ __launch_bounds__(NT, 1)
void ip_fused_kernel(const float* __restrict__ x,
                     const float* __restrict__ gamma,
                     const float* __restrict__ beta,
                     const float* __restrict__ w1,
                     const float* __restrict__ b1,
                     const float* __restrict__ w2,
                     const float* __restrict__ b2,
                     float* __restrict__ out)
{
    extern __shared__ float smem[];
    float* w1s = smem + OFF_W1;
    float* w2s = smem + OFF_W2;
    float* xns = smem + OFF_XN;
    float* hs  = smem + OFF_H;
    float* b1r = smem + OFF_B1R;
    float* b2r = smem + OFF_B2R;
    float* gs  = smem + OFF_G;
    float* bts = smem + OFF_BT;

    const int tid  = threadIdx.x;
    const int warp = tid >> 5;
    const long long row0 = (long long)blockIdx.x * ROWS;

    // ================= staging (coalesced, vectorized where possible) ======
    // w1 [25x128] -> w1s [32x132] zero-padded, TF32-rounded
    for (int i = tid; i < DK * DP; i += NT) {
        int k = i >> 7, p = i & 127;
        float v = (k < DIN) ? w1[k * DP + p] : 0.0f;
        w1s[k * W_LD + p] = wmma::__float_to_tf32(v);
    }
    // w2 [128x128] via float4
    for (int i = tid; i < DP * (DP / 4); i += NT) {
        int k = i >> 5, q4 = i & 31;
        float4 v = reinterpret_cast<const float4*>(w2)[k * 32 + q4];
        float* d = w2s + k * W_LD + q4 * 4;
        d[0] = wmma::__float_to_tf32(v.x);
        d[1] = wmma::__float_to_tf32(v.y);
        d[2] = wmma::__float_to_tf32(v.z);
        d[3] = wmma::__float_to_tf32(v.w);
    }
    // packed x tile (128 rows x 25) -> hs scratch, float4 coalesced
    {
        const float4* xg4 = reinterpret_cast<const float4*>(x + row0 * DIN);
        float4* hs4 = reinterpret_cast<float4*>(hs);
        for (int i = tid; i < ROWS * DIN / 4; i += NT) hs4[i] = xg4[i];
    }
    // replicated bias tiles (16 rows each)
    for (int i = tid; i < 16 * DP; i += NT) {
        int r = i >> 7, c = i & 127;
        b1r[r * W_LD + c] = b1[c];
        b2r[r * W_LD + c] = b2[c];
    }
    if (tid < DK) {
        gs[tid]  = (tid < DIN) ? gamma[tid] : 0.0f;
        bts[tid] = (tid < DIN) ? beta[tid]  : 0.0f;
    }
    __syncthreads();

    // ================= LayerNorm: one thread per row ======================
    if (tid < ROWS) {
        const float* xr = hs + tid * DIN;   // stride 25: gcd(25,32)=1 -> conflict free
        float s = 0.0f, s2 = 0.0f;
        #pragma unroll
        for (int i = 0; i < DIN; i++) { float v = xr[i]; s += v; s2 += v * v; }
        float mu = s * (1.0f / DIN);
        float var = s2 * (1.0f / DIN) - mu * mu;
        float rs = rsqrtf(var + 1e-5f);
        float* xo = xns + tid * XN_LD;
        #pragma unroll
        for (int i = 0; i < DIN; i++)
            xo[i] = wmma::__float_to_tf32((xr[i] - mu) * rs * gs[i] + bts[i]);
        #pragma unroll
        for (int i = DIN; i < DK; i++) xo[i] = 0.0f;
    }
    __syncthreads();

    // warp tile: 16 rows x 64 cols
    const int m0 = (warp >> 1) * 16;
    const int n0 = (warp & 1) * 64;

    // ================= GEMM1: [128x32] x [32x128], acc init = b1 ==========
    wmma::fragment<wmma::accumulator, 16, 16, 8, float> acc[4];
    #pragma unroll
    for (int j = 0; j < 4; j++)
        wmma::load_matrix_sync(acc[j], b1r + n0 + j * 16, W_LD, wmma::mem_row_major);

    #pragma unroll
    for (int k = 0; k < 4; k++) {
        wmma::fragment<wmma::matrix_a, 16, 16, 8, wmma::precision::tf32, wmma::row_major> afr;
        wmma::load_matrix_sync(afr, xns + m0 * XN_LD + k * 8, XN_LD);
        #pragma unroll
        for (int j = 0; j < 4; j++) {
            wmma::fragment<wmma::matrix_b, 16, 16, 8, wmma::precision::tf32, wmma::row_major> bfr;
            wmma::load_matrix_sync(bfr, w1s + (k * 8) * W_LD + n0 + j * 16, W_LD);
            wmma::mma_sync(acc[j], afr, bfr, acc[j]);
        }
    }
    #pragma unroll
    for (int j = 0; j < 4; j++)
        wmma::store_matrix_sync(hs + m0 * W_LD + n0 + j * 16, acc[j], W_LD, wmma::mem_row_major);
    __syncthreads();

    // ================= exact-erf GELU (bias already in acc) ===============
    for (int i = tid; i < ROWS * DP; i += NT) {
        int r = i >> 7, c = i & 127;
        float v = hs[r * W_LD + c];
        float g = 0.5f * v * (1.0f + erff(v * 0.70710678118654752f));
        hs[r * W_LD + c] = wmma::__float_to_tf32(g);
    }
    __syncthreads();

    // ================= GEMM2: [128x128] x [128x128], acc init = b2 ========
    #pragma unroll
    for (int j = 0; j < 4; j++)
        wmma::load_matrix_sync(acc[j], b2r + n0 + j * 16, W_LD, wmma::mem_row_major);

    #pragma unroll
    for (int k = 0; k < 16; k++) {
        wmma::fragment<wmma::matrix_a, 16, 16, 8, wmma::precision::tf32, wmma::row_major> afr;
        wmma::load_matrix_sync(afr, hs + m0 * W_LD + k * 8, W_LD);
        #pragma unroll
        for (int j = 0; j < 4; j++) {
            wmma::fragment<wmma::matrix_b, 16, 16, 8, wmma::precision::tf32, wmma::row_major> bfr;
            wmma::load_matrix_sync(bfr, w2s + (k * 8) * W_LD + n0 + j * 16, W_LD);
            wmma::mma_sync(acc[j], afr, bfr, acc[j]);
        }
    }

    // direct streaming store to global (no shared round-trip, no barrier)
    float* og = out + (row0 + m0) * DP + n0;
    #pragma unroll
    for (int j = 0; j < 4; j++)
        wmma::store_matrix_sync(og + j * 16, acc[j], DP, wmma::mem_row_major);
}

extern "C" void kernel_launch(void* const* d_in, const int* in_sizes, int n_in,
                              void* d_out, int out_size)
{
    const float* x     = (const float*)d_in[0];
    const float* gamma = (const float*)d_in[1];
    const float* beta  = (const float*)d_in[2];
    const float* w1    = (const float*)d_in[3];
    const float* b1    = (const float*)d_in[4];
    const float* w2    = (const float*)d_in[5];
    const float* b2    = (const float*)d_in[6];
    float* out = (float*)d_out;

    static bool attr_set = false;   // one-time attribute set (not a work guard)
    if (!attr_set) {
        cudaFuncSetAttribute(ip_fused_kernel,
                             cudaFuncAttributeMaxDynamicSharedMemorySize,
                             SMEM_BYTES);
        attr_set = true;
    }

    const int rows = in_sizes[0] / DIN;        // 524288
    const int grid = rows / ROWS;              // 4096
    ip_fused_kernel<<<grid, NT, SMEM_BYTES>>>(x, gamma, beta, w1, b1, w2, b2, out);
}

// round 5
// speedup vs baseline: 2.3869x; 1.7379x over previous
#include <cuda_runtime.h>
#include <cuda_fp16.h>
#include <cstdint>
#include <mma.h>

using namespace nvcuda;

#define DIN   25
#define DP    128
#define NT    256        // 8 warps, each owns 16 rows x 128 cols
#define W_LD  136        // halves per row: 272B, 16B-mult, conflict-free under ldmatrix
#define XN_LD 40         // halves per row: 80B
#define B_LDF 136        // floats per row for replicated bias tiles

// shared byte offsets (all 16B aligned)
#define SO_W1  0                         // 32x136 half  = 8704
#define SO_W2  8704                      // 128x136 half = 34816
#define SO_XN  43520                     // 128x40 half  = 10240
#define SO_HS  53760                     // 128x136 half = 34816 (aliases f32 x-stage 12800B)
#define SO_B1R 88576                     // 16x136 f32   = 8704
#define SO_B2R 97280                     // 16x136 f32   = 8704
#define SO_G   105984                    // 128
#define SO_BT  106112                    // 128
#define SMEM_BYTES 106240                // ~103.75 KB -> 2 CTAs/SM

__global__ __launch_bounds__(NT, 2)
void ip_fp16_kernel(const float* __restrict__ x,
                    const float* __restrict__ gamma,
                    const float* __restrict__ beta,
                    const float* __restrict__ w1,
                    const float* __restrict__ b1,
                    const float* __restrict__ w2,
                    const float* __restrict__ b2,
                    float* __restrict__ out)
{
    extern __shared__ char sm[];
    __half* w1s = (__half*)(sm + SO_W1);
    __half* w2s = (__half*)(sm + SO_W2);
    __half* xns = (__half*)(sm + SO_XN);
    __half* hs  = (__half*)(sm + SO_HS);
    float*  b1r = (float*)(sm + SO_B1R);
    float*  b2r = (float*)(sm + SO_B2R);
    float*  gs  = (float*)(sm + SO_G);
    float*  bts = (float*)(sm + SO_BT);
    float*  xstage = (float*)(sm + SO_HS);   // alias: x tile lives here until LN done

    const int tid  = threadIdx.x;
    const int warp = tid >> 5;
    const int lane = tid & 31;
    const long long row0 = (long long)blockIdx.x * 128;

    // ---------------- staging ----------------
    // zero w1s K-pad rows (k=25..31): disjoint from the fill below, no sync needed
    for (int i = tid; i < 476; i += NT)
        ((uint32_t*)(sm + SO_W1 + 25 * W_LD * 2))[i] = 0u;
    // w1 [25x128] -> half
    for (int i = tid; i < DIN * DP; i += NT) {
        int k = i >> 7, n = i & 127;
        w1s[k * W_LD + n] = __float2half_rn(w1[i]);
    }
    // w2 [128x128] -> half via float4
    for (int i = tid; i < DP * DP / 4; i += NT) {
        int k = i >> 5, n4 = i & 31;
        float4 v = ((const float4*)w2)[i];
        __half2 h01 = __floats2half2_rn(v.x, v.y);
        __half2 h23 = __floats2half2_rn(v.z, v.w);
        uint2 u;
        u.x = *(uint32_t*)&h01;
        u.y = *(uint32_t*)&h23;
        *(uint2*)(w2s + k * W_LD + n4 * 4) = u;
    }
    // replicated bias tiles (16 rows)
    for (int i = tid; i < 16 * DP; i += NT) {
        int r = i >> 7, c = i & 127;
        b1r[r * B_LDF + c] = b1[c];
        b2r[r * B_LDF + c] = b2[c];
    }
    if (tid < DIN) { gs[tid] = gamma[tid]; bts[tid] = beta[tid]; }
    // x tile (128x25 f32), coalesced float4
    {
        const float4* xg = (const float4*)(x + row0 * DIN);
        float4* d = (float4*)xstage;
        for (int i = tid; i < 800; i += NT) d[i] = xg[i];
    }
    __syncthreads();

    // ---------------- LayerNorm: one thread per row ----------------
    if (tid < 128) {
        const float* xr = xstage + tid * DIN;   // stride 25: conflict-free
        float s = 0.0f, s2 = 0.0f;
        #pragma unroll
        for (int i = 0; i < DIN; i++) { float v = xr[i]; s += v; s2 += v * v; }
        float mu = s * (1.0f / DIN);
        float rs = rsqrtf(s2 * (1.0f / DIN) - mu * mu + 1e-5f);
        __half* xo = xns + tid * XN_LD;
        #pragma unroll
        for (int i = 0; i < DIN; i++)
            xo[i] = __float2half_rn((xr[i] - mu) * rs * gs[i] + bts[i]);
        #pragma unroll
        for (int i = DIN; i < 32; i++) xo[i] = __half(0.0f);
    }
    __syncthreads();
    // ======== no CTA barriers from here on: warp-private dataflow ========

    const int m0 = warp * 16;

    // ---------------- GEMM1: [16x32] x [32x128], acc init = b1 ----------------
    wmma::fragment<wmma::accumulator, 16, 16, 16, float> acc[8];
    #pragma unroll
    for (int j = 0; j < 8; j++)
        wmma::load_matrix_sync(acc[j], b1r + j * 16, B_LDF, wmma::mem_row_major);

    #pragma unroll
    for (int k = 0; k < 2; k++) {
        wmma::fragment<wmma::matrix_a, 16, 16, 16, __half, wmma::row_major> af;
        wmma::load_matrix_sync(af, xns + m0 * XN_LD + k * 16, XN_LD);
        #pragma unroll
        for (int j = 0; j < 8; j++) {
            wmma::fragment<wmma::matrix_b, 16, 16, 16, __half, wmma::row_major> bf;
            wmma::load_matrix_sync(bf, w1s + (k * 16) * W_LD + j * 16, W_LD);
            wmma::mma_sync(acc[j], af, bf, acc[j]);
        }
    }

    // ---------------- epi1: exact GELU on acc (elementwise), half2 store to hs ----
    // f32 acc layout (sm_80+ de-facto, two m16n8 halves):
    //   pair (i,i+1), i even: row = (lane>>2) + 8*((i>>1)&1), col = 2*(lane&3) + 8*(i>>2)
    {
        const int g  = lane >> 2;
        const int tc = lane & 3;
        #pragma unroll
        for (int j = 0; j < 8; j++) {
            #pragma unroll
            for (int i = 0; i < 8; i += 2) {
                int row = m0 + g + 8 * ((i >> 1) & 1);
                int col = j * 16 + 2 * tc + 8 * (i >> 2);
                float v0 = acc[j].x[i];
                float v1 = acc[j].x[i + 1];
                v0 = 0.5f * v0 * (1.0f + erff(v0 * 0.70710678118654752f));
                v1 = 0.5f * v1 * (1.0f + erff(v1 * 0.70710678118654752f));
                *(__half2*)(hs + row * W_LD + col) = __floats2half2_rn(v0, v1);
            }
        }
        __syncwarp();
    }

    // ---------------- GEMM2: [16x128] x [128x128], acc init = b2 ----------------
    #pragma unroll
    for (int j = 0; j < 8; j++)
        wmma::load_matrix_sync(acc[j], b2r + j * 16, B_LDF, wmma::mem_row_major);

    #pragma unroll
    for (int k = 0; k < 8; k++) {
        wmma::fragment<wmma::matrix_a, 16, 16, 16, __half, wmma::row_major> af;
        wmma::load_matrix_sync(af, hs + m0 * W_LD + k * 16, W_LD);
        #pragma unroll
        for (int j = 0; j < 8; j++) {
            wmma::fragment<wmma::matrix_b, 16, 16, 16, __half, wmma::row_major> bf;
            wmma::load_matrix_sync(bf, w2s + (k * 16) * W_LD + j * 16, W_LD);
            wmma::mma_sync(acc[j], af, bf, acc[j]);
        }
    }

    // ---------------- direct streaming store ----------------
    float* og = out + (row0 + m0) * DP;
    #pragma unroll
    for (int j = 0; j < 8; j++)
        wmma::store_matrix_sync(og + j * 16, acc[j], DP, wmma::mem_row_major);
}

extern "C" void kernel_launch(void* const* d_in, const int* in_sizes, int n_in,
                              void* d_out, int out_size)
{
    const float* x     = (const float*)d_in[0];
    const float* gamma = (const float*)d_in[1];
    const float* beta  = (const float*)d_in[2];
    const float* w1    = (const float*)d_in[3];
    const float* b1    = (const float*)d_in[4];
    const float* w2    = (const float*)d_in[5];
    const float* b2    = (const float*)d_in[6];
    float* out = (float*)d_out;

    static bool attr_set = false;   // one-time attribute set (not a work guard)
    if (!attr_set) {
        cudaFuncSetAttribute(ip_fp16_kernel,
                             cudaFuncAttributeMaxDynamicSharedMemorySize,
                             SMEM_BYTES);
        attr_set = true;
    }

    const int rows = in_sizes[0] / DIN;   // 524288
    const int grid = rows / 128;          // 4096
    ip_fp16_kernel<<<grid, NT, SMEM_BYTES>>>(x, gamma, beta, w1, b1, w2, b2, out);
}

// round 6
// speedup vs baseline: 3.0229x; 1.2665x over previous
#include <cuda_runtime.h>
#include <cuda_fp16.h>
#include <cstdint>

#define DIN   25
#define DP    128
#define NT    128        // 4 warps, each owns 32 rows x 128 cols
#define W_LD  136        // halves per weight row (272B, conflict-free under ldmatrix)
#define XN_LD 40         // halves per xn row (80B)

// shared byte offsets (16B aligned)
#define SO_W1  0         // 32x136 half  = 8704
#define SO_W2  8704      // 128x136 half = 34816
#define SO_XN  43520     // 128x40 half  = 10240
#define SO_XS  53760     // 128x25 f32   = 12800
#define SO_B1  66560     // 512
#define SO_B2  67072     // 512
#define SO_G   67584     // 128
#define SO_BT  67712     // 128
#define SMEM_BYTES 67840 // x3 CTAs = 203.5KB/SM

__device__ __forceinline__ uint32_t s2u(const void* p) {
    uint32_t a;
    asm("{ .reg .u64 t; cvta.to.shared.u64 t, %1; cvt.u32.u64 %0, t; }" : "=r"(a) : "l"(p));
    return a;
}
__device__ __forceinline__ void ldsm4(uint32_t* r, uint32_t addr) {
    asm volatile("ldmatrix.sync.aligned.m8n8.x4.shared.b16 {%0,%1,%2,%3}, [%4];"
                 : "=r"(r[0]), "=r"(r[1]), "=r"(r[2]), "=r"(r[3]) : "r"(addr));
}
__device__ __forceinline__ void ldsm4t(uint32_t* r, uint32_t addr) {
    asm volatile("ldmatrix.sync.aligned.m8n8.x4.trans.shared.b16 {%0,%1,%2,%3}, [%4];"
                 : "=r"(r[0]), "=r"(r[1]), "=r"(r[2]), "=r"(r[3]) : "r"(addr));
}
__device__ __forceinline__ void mma16816(float* c, const uint32_t* a, uint32_t b0, uint32_t b1) {
    asm volatile("mma.sync.aligned.m16n8k16.row.col.f32.f16.f16.f32 "
                 "{%0,%1,%2,%3}, {%4,%5,%6,%7}, {%8,%9}, {%0,%1,%2,%3};"
                 : "+f"(c[0]), "+f"(c[1]), "+f"(c[2]), "+f"(c[3])
                 : "r"(a[0]), "r"(a[1]), "r"(a[2]), "r"(a[3]), "r"(b0), "r"(b1));
}
__device__ __forceinline__ uint32_t packh2(float lo, float hi) {
    __half2 h = __floats2half2_rn(lo, hi);
    return *(uint32_t*)&h;
}
__device__ __forceinline__ float gelu(float v) {
    return 0.5f * v * (1.0f + erff(v * 0.70710678118654752f));
}

__global__ __launch_bounds__(NT, 3)
void ip_mma_kernel(const float* __restrict__ x,
                   const float* __restrict__ gamma,
                   const float* __restrict__ beta,
                   const float* __restrict__ w1,
                   const float* __restrict__ b1,
                   const float* __restrict__ w2,
                   const float* __restrict__ b2,
                   float* __restrict__ out)
{
    extern __shared__ char smc[];
    const uint32_t sb = s2u(smc);
    __half* w1s = (__half*)(smc + SO_W1);
    __half* w2s = (__half*)(smc + SO_W2);
    __half* xns = (__half*)(smc + SO_XN);
    float*  xst = (float*)(smc + SO_XS);
    float*  b1s = (float*)(smc + SO_B1);
    float*  b2s = (float*)(smc + SO_B2);
    float*  gs  = (float*)(smc + SO_G);
    float*  bts = (float*)(smc + SO_BT);

    const int tid  = threadIdx.x;
    const int warp = tid >> 5;
    const int lane = tid & 31;
    const int g    = lane >> 2;       // row group 0..7
    const int tc   = lane & 3;        // col pair  0..3
    const long long row0 = (long long)blockIdx.x * 128;

    // ---------------- staging ----------------
    for (int i = tid; i < 476; i += NT)                       // zero w1 K-pad rows 25..31
        ((uint32_t*)(smc + SO_W1 + 25 * W_LD * 2))[i] = 0u;
    for (int i = tid; i < DIN * DP; i += NT) {                // w1 [25x128] -> half
        int k = i >> 7, n = i & 127;
        w1s[k * W_LD + n] = __float2half_rn(w1[i]);
    }
    for (int i = tid; i < DP * DP / 4; i += NT) {             // w2 [128x128] -> half
        int k = i >> 5, n4 = i & 31;
        float4 v = ((const float4*)w2)[i];
        __half2 h01 = __floats2half2_rn(v.x, v.y);
        __half2 h23 = __floats2half2_rn(v.z, v.w);
        uint2 u;
        u.x = *(uint32_t*)&h01; u.y = *(uint32_t*)&h23;
        *(uint2*)(w2s + k * W_LD + n4 * 4) = u;
    }
    if (tid < DP) { b1s[tid] = b1[tid]; b2s[tid] = b2[tid]; }
    if (tid < DIN) { gs[tid] = gamma[tid]; bts[tid] = beta[tid]; }
    {
        const float4* xg = (const float4*)(x + row0 * DIN);
        float4* d = (float4*)xst;
        for (int i = tid; i < 800; i += NT) d[i] = xg[i];
    }
    __syncthreads();

    // ---------------- LayerNorm: thread tid -> row tid ----------------
    {
        const float* xr = xst + tid * DIN;     // stride 25: conflict-free
        float s = 0.0f, s2 = 0.0f;
        #pragma unroll
        for (int i = 0; i < DIN; i++) { float v = xr[i]; s += v; s2 += v * v; }
        float mu = s * (1.0f / DIN);
        float rs = rsqrtf(s2 * (1.0f / DIN) - mu * mu + 1e-5f);
        __half* xo = xns + tid * XN_LD;
        #pragma unroll
        for (int i = 0; i < DIN; i++)
            xo[i] = __float2half_rn((xr[i] - mu) * rs * gs[i] + bts[i]);
        #pragma unroll
        for (int i = DIN; i < 32; i++) xo[i] = __half(0.0f);
    }
    __syncwarp();   // warp w's xn rows (32w..32w+31) were written by warp w itself

    const int trow0 = warp * 32;

    // per-lane ldmatrix base addresses
    const int lrow = ((lane >> 3) & 1) * 8 + (lane & 7);      // row within 16x16 tile
    const int lcol = ((lane >> 4) & 1) * 8;                   // col within 16x16 tile
    const uint32_t xl  = sb + SO_XN + ((trow0 + lrow) * XN_LD + lcol) * 2;
    const uint32_t w1l = sb + SO_W1 + (lrow * W_LD + lcol) * 2;
    const uint32_t w2l = sb + SO_W2 + (lrow * W_LD + lcol) * 2;

    // ================= GEMM1 + GELU -> register A2 fragments =================
    uint32_t a2[2][8][4];   // [m-tile][k-slice][frag reg]

    #pragma unroll
    for (int mt = 0; mt < 2; mt++) {
        float c1[16][4];
        #pragma unroll
        for (int j = 0; j < 16; j++) {                        // acc init = b1
            float2 bv = *(float2*)&b1s[8 * j + 2 * tc];
            c1[j][0] = bv.x; c1[j][1] = bv.y; c1[j][2] = bv.x; c1[j][3] = bv.y;
        }
        #pragma unroll
        for (int kk = 0; kk < 2; kk++) {
            uint32_t a[4];
            ldsm4(a, xl + (16 * mt * XN_LD + 16 * kk) * 2);
            #pragma unroll
            for (int nt = 0; nt < 8; nt++) {
                uint32_t b[4];
                ldsm4t(b, w1l + (16 * kk * W_LD + 16 * nt) * 2);
                mma16816(c1[2 * nt],     a, b[0], b[1]);
                mma16816(c1[2 * nt + 1], a, b[2], b[3]);
            }
        }
        // GELU in registers, pack acc pairs -> A fragments for GEMM2
        #pragma unroll
        for (int ks = 0; ks < 8; ks++) {
            a2[mt][ks][0] = packh2(gelu(c1[2*ks][0]),   gelu(c1[2*ks][1]));
            a2[mt][ks][1] = packh2(gelu(c1[2*ks][2]),   gelu(c1[2*ks][3]));
            a2[mt][ks][2] = packh2(gelu(c1[2*ks+1][0]), gelu(c1[2*ks+1][1]));
            a2[mt][ks][3] = packh2(gelu(c1[2*ks+1][2]), gelu(c1[2*ks+1][3]));
        }
    }

    // ================= GEMM2 in two n-halves (bounds registers) ==============
    #pragma unroll
    for (int nh = 0; nh < 2; nh++) {
        float c2[2][8][4];
        #pragma unroll
        for (int mt = 0; mt < 2; mt++)
            #pragma unroll
            for (int j = 0; j < 8; j++) {                     // acc init = b2
                float2 bv = *(float2*)&b2s[64 * nh + 8 * j + 2 * tc];
                c2[mt][j][0] = bv.x; c2[mt][j][1] = bv.y;
                c2[mt][j][2] = bv.x; c2[mt][j][3] = bv.y;
            }
        #pragma unroll
        for (int ks = 0; ks < 8; ks++) {
            #pragma unroll
            for (int nt = 0; nt < 4; nt++) {
                uint32_t b[4];
                ldsm4t(b, w2l + (16 * ks * W_LD + 64 * nh + 16 * nt) * 2);
                #pragma unroll
                for (int mt = 0; mt < 2; mt++) {
                    mma16816(c2[mt][2 * nt],     a2[mt][ks], b[0], b[1]);
                    mma16816(c2[mt][2 * nt + 1], a2[mt][ks], b[2], b[3]);
                }
            }
        }
        // epilogue: direct coalesced-by-warp float2 stores
        #pragma unroll
        for (int mt = 0; mt < 2; mt++) {
            long long r = row0 + trow0 + 16 * mt + g;
            #pragma unroll
            for (int j = 0; j < 8; j++) {
                int col = 64 * nh + 8 * j + 2 * tc;
                *(float2*)(out + r * DP + col)       = make_float2(c2[mt][j][0], c2[mt][j][1]);
                *(float2*)(out + (r + 8) * DP + col) = make_float2(c2[mt][j][2], c2[mt][j][3]);
            }
        }
    }
}

extern "C" void kernel_launch(void* const* d_in, const int* in_sizes, int n_in,
                              void* d_out, int out_size)
{
    const float* x     = (const float*)d_in[0];
    const float* gamma = (const float*)d_in[1];
    const float* beta  = (const float*)d_in[2];
    const float* w1    = (const float*)d_in[3];
    const float* b1    = (const float*)d_in[4];
    const float* w2    = (const float*)d_in[5];
    const float* b2    = (const float*)d_in[6];
    float* out = (float*)d_out;

    static bool attr_set = false;   // one-time attribute set (not a work guard)
    if (!attr_set) {
        cudaFuncSetAttribute(ip_mma_kernel,
                             cudaFuncAttributeMaxDynamicSharedMemorySize,
                             SMEM_BYTES);
        attr_set = true;
    }

    const int rows = in_sizes[0] / DIN;   // 524288
    const int grid = rows / 128;          // 4096
    ip_mma_kernel<<<grid, NT, SMEM_BYTES>>>(x, gamma, beta, w1, b1, w2, b2, out);
}

// round 7
// speedup vs baseline: 5.1823x; 1.7143x over previous
#include <cuda_runtime.h>
#include <cuda_fp16.h>
#include <cstdint>

#define DIN   25
#define DP    128
#define NT    128        // 4 warps, each owns 32 rows x 128 cols
#define W_LD  136        // halves per weight row (272B, conflict-free under ldmatrix)
#define XN_LD 40         // halves per xn row (80B)

// shared byte offsets (16B aligned)
#define SO_W1  0         // 32x136 half  = 8704
#define SO_W2  8704      // 128x136 half = 34816
#define SO_XN  43520     // 128x40 half  = 10240
#define SO_B1  53760     // 512
#define SO_B2  54272     // 512
#define SO_G   54784     // 128
#define SO_BT  54912     // 128
#define SMEM_BYTES 55040 // x4 CTAs = 215KB/SM

__device__ __forceinline__ uint32_t s2u(const void* p) {
    uint32_t a;
    asm("{ .reg .u64 t; cvta.to.shared.u64 t, %1; cvt.u32.u64 %0, t; }" : "=r"(a) : "l"(p));
    return a;
}
__device__ __forceinline__ void ldsm4(uint32_t* r, uint32_t addr) {
    asm volatile("ldmatrix.sync.aligned.m8n8.x4.shared.b16 {%0,%1,%2,%3}, [%4];"
                 : "=r"(r[0]), "=r"(r[1]), "=r"(r[2]), "=r"(r[3]) : "r"(addr));
}
__device__ __forceinline__ void ldsm4t(uint32_t* r, uint32_t addr) {
    asm volatile("ldmatrix.sync.aligned.m8n8.x4.trans.shared.b16 {%0,%1,%2,%3}, [%4];"
                 : "=r"(r[0]), "=r"(r[1]), "=r"(r[2]), "=r"(r[3]) : "r"(addr));
}
__device__ __forceinline__ void mma16816(float* c, const uint32_t* a, uint32_t b0, uint32_t b1) {
    asm volatile("mma.sync.aligned.m16n8k16.row.col.f32.f16.f16.f32 "
                 "{%0,%1,%2,%3}, {%4,%5,%6,%7}, {%8,%9}, {%0,%1,%2,%3};"
                 : "+f"(c[0]), "+f"(c[1]), "+f"(c[2]), "+f"(c[3])
                 : "r"(a[0]), "r"(a[1]), "r"(a[2]), "r"(a[3]), "r"(b0), "r"(b1));
}
__device__ __forceinline__ uint32_t packh2(float lo, float hi) {
    __half2 h = __floats2half2_rn(lo, hi);
    return *(uint32_t*)&h;
}
__device__ __forceinline__ float gelu(float v) {
    return 0.5f * v * (1.0f + erff(v * 0.70710678118654752f));
}

__global__ __launch_bounds__(NT, 4)
void ip_mma_kernel(const float* __restrict__ x,
                   const float* __restrict__ gamma,
                   const float* __restrict__ beta,
                   const float* __restrict__ w1,
                   const float* __restrict__ b1,
                   const float* __restrict__ w2,
                   const float* __restrict__ b2,
                   float* __restrict__ out)
{
    extern __shared__ char smc[];
    const uint32_t sb = s2u(smc);
    __half* w1s = (__half*)(smc + SO_W1);
    __half* w2s = (__half*)(smc + SO_W2);
    __half* xns = (__half*)(smc + SO_XN);
    float*  b1s = (float*)(smc + SO_B1);
    float*  b2s = (float*)(smc + SO_B2);
    float*  gs  = (float*)(smc + SO_G);
    float*  bts = (float*)(smc + SO_BT);

    const int tid  = threadIdx.x;
    const int warp = tid >> 5;
    const int lane = tid & 31;
    const int g    = lane >> 2;       // row group 0..7
    const int tc   = lane & 3;        // col pair  0..3
    const long long row0 = (long long)blockIdx.x * 128;

    // ---------------- staging ----------------
    for (int i = tid; i < 476; i += NT)                       // zero w1 K-pad rows 25..31
        ((uint32_t*)(smc + SO_W1 + 25 * W_LD * 2))[i] = 0u;
    for (int i = tid; i < DIN * DP; i += NT) {                // w1 [25x128] -> half
        int k = i >> 7, n = i & 127;
        w1s[k * W_LD + n] = __float2half_rn(w1[i]);
    }
    for (int i = tid; i < DP * DP / 4; i += NT) {             // w2 [128x128] -> half
        int k = i >> 5, n4 = i & 31;
        float4 v = ((const float4*)w2)[i];
        __half2 h01 = __floats2half2_rn(v.x, v.y);
        __half2 h23 = __floats2half2_rn(v.z, v.w);
        uint2 u;
        u.x = *(uint32_t*)&h01; u.y = *(uint32_t*)&h23;
        *(uint2*)(w2s + k * W_LD + n4 * 4) = u;
    }
    if (tid < DP) { b1s[tid] = b1[tid]; b2s[tid] = b2[tid]; }
    if (tid < DIN) { gs[tid] = gamma[tid]; bts[tid] = beta[tid]; }
    __syncthreads();

    // -------- LayerNorm: thread tid -> row tid, x read direct from global ----
    {
        const float* xr = x + (row0 + tid) * DIN;
        float v[DIN];
        float s = 0.0f, s2 = 0.0f;
        #pragma unroll
        for (int i = 0; i < DIN; i++) { v[i] = xr[i]; s += v[i]; s2 += v[i] * v[i]; }
        float mu = s * (1.0f / DIN);
        float rs = rsqrtf(s2 * (1.0f / DIN) - mu * mu + 1e-5f);
        __half* xo = xns + tid * XN_LD;
        #pragma unroll
        for (int i = 0; i < DIN; i++)
            xo[i] = __float2half_rn((v[i] - mu) * rs * gs[i] + bts[i]);
        #pragma unroll
        for (int i = DIN; i < 32; i++) xo[i] = __half(0.0f);
    }
    __syncwarp();   // warp w's xn rows (32w..32w+31) written by warp w itself

    const int trow0 = warp * 32;

    // per-lane ldmatrix base addresses
    const int lrow = ((lane >> 3) & 1) * 8 + (lane & 7);      // row within 16x16 tile
    const int lcol = ((lane >> 4) & 1) * 8;                   // col within 16x16 tile
    const uint32_t xl  = sb + SO_XN + ((trow0 + lrow) * XN_LD + lcol) * 2;
    const uint32_t w1l = sb + SO_W1 + (lrow * W_LD + lcol) * 2;
    const uint32_t w2l = sb + SO_W2 + (lrow * W_LD + lcol) * 2;

    // ================= GEMM1 + GELU -> register A2 fragments =================
    uint32_t afr[2][2][4];                 // A1 frags: [m-tile][k-slice]
    #pragma unroll
    for (int mt = 0; mt < 2; mt++)
        #pragma unroll
        for (int kk = 0; kk < 2; kk++)
            ldsm4(afr[mt][kk], xl + (16 * mt * XN_LD + 16 * kk) * 2);

    uint32_t a2[2][8][4];                  // GEMM2 A frags (half2-packed)
    #pragma unroll
    for (int nt = 0; nt < 8; nt++) {
        uint32_t b[2][4];
        ldsm4t(b[0], w1l + (16 * nt) * 2);
        ldsm4t(b[1], w1l + (16 * W_LD + 16 * nt) * 2);
        float2 bv0 = *(const float2*)&b1s[16 * nt + 2 * tc];
        float2 bv1 = *(const float2*)&b1s[16 * nt + 8 + 2 * tc];
        #pragma unroll
        for (int mt = 0; mt < 2; mt++) {
            float c0[4] = {bv0.x, bv0.y, bv0.x, bv0.y};
            float c1[4] = {bv1.x, bv1.y, bv1.x, bv1.y};
            #pragma unroll
            for (int kk = 0; kk < 2; kk++) {
                mma16816(c0, afr[mt][kk], b[kk][0], b[kk][1]);
                mma16816(c1, afr[mt][kk], b[kk][2], b[kk][3]);
            }
            a2[mt][nt][0] = packh2(gelu(c0[0]), gelu(c0[1]));
            a2[mt][nt][1] = packh2(gelu(c0[2]), gelu(c0[3]));
            a2[mt][nt][2] = packh2(gelu(c1[0]), gelu(c1[1]));
            a2[mt][nt][3] = packh2(gelu(c1[2]), gelu(c1[3]));
        }
    }

    // ================= GEMM2 in four n-quarters (regs <= 128) ================
    #pragma unroll
    for (int nq = 0; nq < 4; nq++) {
        float c2[2][4][4];
        #pragma unroll
        for (int mt = 0; mt < 2; mt++)
            #pragma unroll
            for (int j = 0; j < 4; j++) {                     // acc init = b2
                float2 bv = *(const float2*)&b2s[32 * nq + 8 * j + 2 * tc];
                c2[mt][j][0] = bv.x; c2[mt][j][1] = bv.y;
                c2[mt][j][2] = bv.x; c2[mt][j][3] = bv.y;
            }
        #pragma unroll
        for (int ks = 0; ks < 8; ks++) {
            #pragma unroll
            for (int nt = 0; nt < 2; nt++) {
                uint32_t b[4];
                ldsm4t(b, w2l + (16 * ks * W_LD + 32 * nq + 16 * nt) * 2);
                #pragma unroll
                for (int mt = 0; mt < 2; mt++) {
                    mma16816(c2[mt][2 * nt],     a2[mt][ks], b[0], b[1]);
                    mma16816(c2[mt][2 * nt + 1], a2[mt][ks], b[2], b[3]);
                }
            }
        }
        // epilogue: direct coalesced-by-warp float2 stores
        #pragma unroll
        for (int mt = 0; mt < 2; mt++) {
            long long r = row0 + trow0 + 16 * mt + g;
            #pragma unroll
            for (int j = 0; j < 4; j++) {
                int col = 32 * nq + 8 * j + 2 * tc;
                *(float2*)(out + r * DP + col)       = make_float2(c2[mt][j][0], c2[mt][j][1]);
                *(float2*)(out + (r + 8) * DP + col) = make_float2(c2[mt][j][2], c2[mt][j][3]);
            }
        }
    }
}

extern "C" void kernel_launch(void* const* d_in, const int* in_sizes, int n_in,
                              void* d_out, int out_size)
{
    const float* x     = (const float*)d_in[0];
    const float* gamma = (const float*)d_in[1];
    const float* beta  = (const float*)d_in[2];
    const float* w1    = (const float*)d_in[3];
    const float* b1    = (const float*)d_in[4];
    const float* w2    = (const float*)d_in[5];
    const float* b2    = (const float*)d_in[6];
    float* out = (float*)d_out;

    static bool attr_set = false;   // one-time attribute set (not a work guard)
    if (!attr_set) {
        cudaFuncSetAttribute(ip_mma_kernel,
                             cudaFuncAttributeMaxDynamicSharedMemorySize,
                             SMEM_BYTES);
        attr_set = true;
    }

    const int rows = in_sizes[0] / DIN;   // 524288
    const int grid = rows / 128;          // 4096
    ip_mma_kernel<<<grid, NT, SMEM_BYTES>>>(x, gamma, beta, w1, b1, w2, b2, out);
}

// round 8
// speedup vs baseline: 5.2813x; 1.0191x over previous
#include <cuda_runtime.h>
#include <cuda_fp16.h>
#include <cstdint>

#define DIN   25
#define DP    128
#define NT    128        // 4 warps, each owns 32 rows x 128 cols per tile
#define W_LD  136        // halves per weight row (272B, conflict-free under ldmatrix)
#define XN_LD 40         // halves per xn row (80B)

// shared byte offsets (16B aligned)
#define SO_W1  0         // 32x136 half  = 8704
#define SO_W2  8704      // 128x136 half = 34816
#define SO_XN  43520     // 128x40 half  = 10240
#define SO_B1  53760     // 512
#define SO_B2  54272     // 512
#define SO_G   54784     // 128
#define SO_BT  54912     // 128
#define SMEM_BYTES 55040 // x4 CTAs = 215KB/SM

__device__ __forceinline__ uint32_t s2u(const void* p) {
    uint32_t a;
    asm("{ .reg .u64 t; cvta.to.shared.u64 t, %1; cvt.u32.u64 %0, t; }" : "=r"(a) : "l"(p));
    return a;
}
__device__ __forceinline__ void ldsm4(uint32_t* r, uint32_t addr) {
    asm volatile("ldmatrix.sync.aligned.m8n8.x4.shared.b16 {%0,%1,%2,%3}, [%4];"
                 : "=r"(r[0]), "=r"(r[1]), "=r"(r[2]), "=r"(r[3]) : "r"(addr));
}
__device__ __forceinline__ void ldsm4t(uint32_t* r, uint32_t addr) {
    asm volatile("ldmatrix.sync.aligned.m8n8.x4.trans.shared.b16 {%0,%1,%2,%3}, [%4];"
                 : "=r"(r[0]), "=r"(r[1]), "=r"(r[2]), "=r"(r[3]) : "r"(addr));
}
__device__ __forceinline__ void mma16816(float* c, const uint32_t* a, uint32_t b0, uint32_t b1) {
    asm volatile("mma.sync.aligned.m16n8k16.row.col.f32.f16.f16.f32 "
                 "{%0,%1,%2,%3}, {%4,%5,%6,%7}, {%8,%9}, {%0,%1,%2,%3};"
                 : "+f"(c[0]), "+f"(c[1]), "+f"(c[2]), "+f"(c[3])
                 : "r"(a[0]), "r"(a[1]), "r"(a[2]), "r"(a[3]), "r"(b0), "r"(b1));
}
__device__ __forceinline__ uint32_t packh2(float lo, float hi) {
    __half2 h = __floats2half2_rn(lo, hi);
    return *(uint32_t*)&h;
}
__device__ __forceinline__ float gelu(float v) {
    return 0.5f * v * (1.0f + erff(v * 0.70710678118654752f));
}
__device__ __forceinline__ void pfL2(const void* p) {
    asm volatile("prefetch.global.L2 [%0];" :: "l"(p));
}

__global__ __launch_bounds__(NT, 4)
void ip_mma_kernel(const float* __restrict__ x,
                   const float* __restrict__ gamma,
                   const float* __restrict__ beta,
                   const float* __restrict__ w1,
                   const float* __restrict__ b1,
                   const float* __restrict__ w2,
                   const float* __restrict__ b2,
                   float* __restrict__ out, int ntiles)
{
    extern __shared__ char smc[];
    const uint32_t sb = s2u(smc);
    __half* w1s = (__half*)(smc + SO_W1);
    __half* w2s = (__half*)(smc + SO_W2);
    __half* xns = (__half*)(smc + SO_XN);
    float*  b1s = (float*)(smc + SO_B1);
    float*  b2s = (float*)(smc + SO_B2);
    float*  gs  = (float*)(smc + SO_G);
    float*  bts = (float*)(smc + SO_BT);

    const int tid  = threadIdx.x;
    const int warp = tid >> 5;
    const int lane = tid & 31;
    const int g    = lane >> 2;       // row group 0..7
    const int tc   = lane & 3;        // col pair  0..3

    // ---------------- one-time staging ----------------
    for (int i = tid; i < 476; i += NT)                       // zero w1 K-pad rows 25..31
        ((uint32_t*)(smc + SO_W1 + 25 * W_LD * 2))[i] = 0u;
    for (int i = tid; i < DIN * DP; i += NT) {                // w1 [25x128] -> half
        int k = i >> 7, n = i & 127;
        w1s[k * W_LD + n] = __float2half_rn(w1[i]);
    }
    for (int i = tid; i < DP * DP / 4; i += NT) {             // w2 [128x128] -> half
        int k = i >> 5, n4 = i & 31;
        float4 v = ((const float4*)w2)[i];
        __half2 h01 = __floats2half2_rn(v.x, v.y);
        __half2 h23 = __floats2half2_rn(v.z, v.w);
        uint2 u;
        u.x = *(uint32_t*)&h01; u.y = *(uint32_t*)&h23;
        *(uint2*)(w2s + k * W_LD + n4 * 4) = u;
    }
    if (tid < DP) { b1s[tid] = b1[tid]; b2s[tid] = b2[tid]; }
    if (tid < DIN) { gs[tid] = gamma[tid]; bts[tid] = beta[tid]; }
    __syncthreads();
    // ======== no CTA barriers from here on ========

    const int trow0 = warp * 32;
    const int lrow = ((lane >> 3) & 1) * 8 + (lane & 7);      // row within 16x16 tile
    const int lcol = ((lane >> 4) & 1) * 8;                   // col within 16x16 tile
    const uint32_t xl  = sb + SO_XN + ((trow0 + lrow) * XN_LD + lcol) * 2;
    const uint32_t w1l = sb + SO_W1 + (lrow * W_LD + lcol) * 2;
    const uint32_t w2l = sb + SO_W2 + (lrow * W_LD + lcol) * 2;

    // ---------------- persistent tile loop ----------------
    for (int t = blockIdx.x; t < ntiles; t += gridDim.x) {
        const long long row0 = (long long)t * 128;

        // prefetch next tile's x rows to L2 (hidden under this tile's GEMMs)
        {
            int tn = t + gridDim.x;
            if (tn < ntiles) {
                const char* pf = (const char*)(x + ((long long)tn * 128 + tid) * DIN);
                pfL2(pf); pfL2(pf + 96);
            }
        }

        // ---- LayerNorm: thread tid -> row tid, x direct from global ----
        {
            const float* xr = x + (row0 + tid) * DIN;
            float v[DIN];
            float s = 0.0f, s2 = 0.0f;
            #pragma unroll
            for (int i = 0; i < DIN; i++) { v[i] = xr[i]; s += v[i]; s2 += v[i] * v[i]; }
            float mu = s * (1.0f / DIN);
            float rs = rsqrtf(s2 * (1.0f / DIN) - mu * mu + 1e-5f);
            __half* xo = xns + tid * XN_LD;
            #pragma unroll
            for (int i = 0; i < DIN; i++)
                xo[i] = __float2half_rn((v[i] - mu) * rs * gs[i] + bts[i]);
            #pragma unroll
            for (int i = DIN; i < 32; i++) xo[i] = __half(0.0f);
        }
        __syncwarp();   // warp w's xn rows written by warp w itself

        // ================= GEMM1 + GELU -> register A2 fragments ============
        uint32_t afr[2][2][4];
        #pragma unroll
        for (int mt = 0; mt < 2; mt++)
            #pragma unroll
            for (int kk = 0; kk < 2; kk++)
                ldsm4(afr[mt][kk], xl + (16 * mt * XN_LD + 16 * kk) * 2);

        uint32_t a2[2][8][4];
        #pragma unroll
        for (int nt = 0; nt < 8; nt++) {
            uint32_t b[2][4];
            ldsm4t(b[0], w1l + (16 * nt) * 2);
            ldsm4t(b[1], w1l + (16 * W_LD + 16 * nt) * 2);
            float2 bv0 = *(const float2*)&b1s[16 * nt + 2 * tc];
            float2 bv1 = *(const float2*)&b1s[16 * nt + 8 + 2 * tc];
            #pragma unroll
            for (int mt = 0; mt < 2; mt++) {
                float c0[4] = {bv0.x, bv0.y, bv0.x, bv0.y};
                float c1[4] = {bv1.x, bv1.y, bv1.x, bv1.y};
                #pragma unroll
                for (int kk = 0; kk < 2; kk++) {
                    mma16816(c0, afr[mt][kk], b[kk][0], b[kk][1]);
                    mma16816(c1, afr[mt][kk], b[kk][2], b[kk][3]);
                }
                a2[mt][nt][0] = packh2(gelu(c0[0]), gelu(c0[1]));
                a2[mt][nt][1] = packh2(gelu(c0[2]), gelu(c0[3]));
                a2[mt][nt][2] = packh2(gelu(c1[0]), gelu(c1[1]));
                a2[mt][nt][3] = packh2(gelu(c1[2]), gelu(c1[3]));
            }
        }

        // ================= GEMM2 in four n-quarters (regs <= 128) ===========
        #pragma unroll
        for (int nq = 0; nq < 4; nq++) {
            float c2[2][4][4];
            #pragma unroll
            for (int mt = 0; mt < 2; mt++)
                #pragma unroll
                for (int j = 0; j < 4; j++) {                 // acc init = b2
                    float2 bv = *(const float2*)&b2s[32 * nq + 8 * j + 2 * tc];
                    c2[mt][j][0] = bv.x; c2[mt][j][1] = bv.y;
                    c2[mt][j][2] = bv.x; c2[mt][j][3] = bv.y;
                }
            #pragma unroll
            for (int ks = 0; ks < 8; ks++) {
                #pragma unroll
                for (int nt = 0; nt < 2; nt++) {
                    uint32_t b[4];
                    ldsm4t(b, w2l + (16 * ks * W_LD + 32 * nq + 16 * nt) * 2);
                    #pragma unroll
                    for (int mt = 0; mt < 2; mt++) {
                        mma16816(c2[mt][2 * nt],     a2[mt][ks], b[0], b[1]);
                        mma16816(c2[mt][2 * nt + 1], a2[mt][ks], b[2], b[3]);
                    }
                }
            }
            // epilogue: direct coalesced-by-warp float2 stores
            #pragma unroll
            for (int mt = 0; mt < 2; mt++) {
                long long r = row0 + trow0 + 16 * mt + g;
                #pragma unroll
                for (int j = 0; j < 4; j++) {
                    int col = 32 * nq + 8 * j + 2 * tc;
                    *(float2*)(out + r * DP + col)       = make_float2(c2[mt][j][0], c2[mt][j][1]);
                    *(float2*)(out + (r + 8) * DP + col) = make_float2(c2[mt][j][2], c2[mt][j][3]);
                }
            }
        }
    }
}

extern "C" void kernel_launch(void* const* d_in, const int* in_sizes, int n_in,
                              void* d_out, int out_size)
{
    const float* x     = (const float*)d_in[0];
    const float* gamma = (const float*)d_in[1];
    const float* beta  = (const float*)d_in[2];
    const float* w1    = (const float*)d_in[3];
    const float* b1    = (const float*)d_in[4];
    const float* w2    = (const float*)d_in[5];
    const float* b2    = (const float*)d_in[6];
    float* out = (float*)d_out;

    static int n_sm = 0;   // one-time query + attribute set (not a work guard)
    if (n_sm == 0) {
        cudaDeviceProp prop;
        cudaGetDeviceProperties(&prop, 0);
        n_sm = prop.multiProcessorCount;
        cudaFuncSetAttribute(ip_mma_kernel,
                             cudaFuncAttributeMaxDynamicSharedMemorySize,
                             SMEM_BYTES);
    }

    const int rows = in_sizes[0] / DIN;   // 524288
    const int ntiles = rows / 128;        // 4096
    const int grid = n_sm * 4;            // persistent: 4 CTAs/SM
    ip_mma_kernel<<<grid, NT, SMEM_BYTES>>>(x, gamma, beta, w1, b1, w2, b2, out, ntiles);
}

// round 9
// speedup vs baseline: 5.9340x; 1.1236x over previous
#include <cuda_runtime.h>
#include <cuda_fp16.h>
#include <cstdint>

#define DIN   25
#define DP    128
#define NT    256        // 8 warps; warp w owns rows 32w..32w+31 of a 256-row tile
#define TROWS 256        // rows per CTA tile
#define W_LD  136        // halves per weight row (272B, conflict-free under ldmatrix)
#define XN_LD 40         // halves per xn row (80B)

// shared byte offsets (16B aligned)
#define SO_W1  0         // 32x136 half   = 8704
#define SO_W2  8704      // 128x136 half  = 34816
#define SO_XN  43520     // 256x40 half   = 20480
#define SO_XS  64000     // 256x25 f32    = 25600
#define SO_B1  89600     // 512
#define SO_B2  90112     // 512
#define SO_G   90624     // 128
#define SO_BT  90752     // 128
#define SMEM_BYTES 90880 // x2 CTAs = 177.5KB/SM (<= 228KB)

__device__ __forceinline__ uint32_t s2u(const void* p) {
    uint32_t a;
    asm("{ .reg .u64 t; cvta.to.shared.u64 t, %1; cvt.u32.u64 %0, t; }" : "=r"(a) : "l"(p));
    return a;
}
__device__ __forceinline__ void ldsm4(uint32_t* r, uint32_t addr) {
    asm volatile("ldmatrix.sync.aligned.m8n8.x4.shared.b16 {%0,%1,%2,%3}, [%4];"
                 : "=r"(r[0]), "=r"(r[1]), "=r"(r[2]), "=r"(r[3]) : "r"(addr));
}
__device__ __forceinline__ void ldsm4t(uint32_t* r, uint32_t addr) {
    asm volatile("ldmatrix.sync.aligned.m8n8.x4.trans.shared.b16 {%0,%1,%2,%3}, [%4];"
                 : "=r"(r[0]), "=r"(r[1]), "=r"(r[2]), "=r"(r[3]) : "r"(addr));
}
__device__ __forceinline__ void mma16816(float* c, const uint32_t* a, uint32_t b0, uint32_t b1) {
    asm volatile("mma.sync.aligned.m16n8k16.row.col.f32.f16.f16.f32 "
                 "{%0,%1,%2,%3}, {%4,%5,%6,%7}, {%8,%9}, {%0,%1,%2,%3};"
                 : "+f"(c[0]), "+f"(c[1]), "+f"(c[2]), "+f"(c[3])
                 : "r"(a[0]), "r"(a[1]), "r"(a[2]), "r"(a[3]), "r"(b0), "r"(b1));
}
__device__ __forceinline__ uint32_t packh2(float lo, float hi) {
    __half2 h = __floats2half2_rn(lo, hi);
    return *(uint32_t*)&h;
}
__device__ __forceinline__ float gelu(float v) {
    return 0.5f * v * (1.0f + erff(v * 0.70710678118654752f));
}
__device__ __forceinline__ void pfL2(const void* p) {
    asm volatile("prefetch.global.L2 [%0];" :: "l"(p));
}

__global__ __launch_bounds__(NT, 2)
void ip_mma_kernel(const float* __restrict__ x,
                   const float* __restrict__ gamma,
                   const float* __restrict__ beta,
                   const float* __restrict__ w1,
                   const float* __restrict__ b1,
                   const float* __restrict__ w2,
                   const float* __restrict__ b2,
                   float* __restrict__ out, int ntiles)
{
    extern __shared__ char smc[];
    const uint32_t sb = s2u(smc);
    __half* w1s = (__half*)(smc + SO_W1);
    __half* w2s = (__half*)(smc + SO_W2);
    __half* xns = (__half*)(smc + SO_XN);
    float*  xst = (float*)(smc + SO_XS);
    float*  b1s = (float*)(smc + SO_B1);
    float*  b2s = (float*)(smc + SO_B2);
    float*  gs  = (float*)(smc + SO_G);
    float*  bts = (float*)(smc + SO_BT);

    const int tid  = threadIdx.x;
    const int warp = tid >> 5;
    const int lane = tid & 31;
    const int g    = lane >> 2;       // row group 0..7
    const int tc   = lane & 3;        // col pair  0..3

    // ---------------- one-time staging ----------------
    for (int i = tid; i < 476; i += NT)                       // zero w1 K-pad rows 25..31
        ((uint32_t*)(smc + SO_W1 + 25 * W_LD * 2))[i] = 0u;
    for (int i = tid; i < DIN * DP; i += NT) {                // w1 [25x128] -> half
        int k = i >> 7, n = i & 127;
        w1s[k * W_LD + n] = __float2half_rn(w1[i]);
    }
    for (int i = tid; i < DP * DP / 4; i += NT) {             // w2 [128x128] -> half
        int k = i >> 5, n4 = i & 31;
        float4 v = ((const float4*)w2)[i];
        __half2 h01 = __floats2half2_rn(v.x, v.y);
        __half2 h23 = __floats2half2_rn(v.z, v.w);
        uint2 u;
        u.x = *(uint32_t*)&h01; u.y = *(uint32_t*)&h23;
        *(uint2*)(w2s + k * W_LD + n4 * 4) = u;
    }
    if (tid < DP) { b1s[tid] = b1[tid]; b2s[tid] = b2[tid]; }
    if (tid < DIN) { gs[tid] = gamma[tid]; bts[tid] = beta[tid]; }

    const int trow0 = warp * 32;
    const int lrow = ((lane >> 3) & 1) * 8 + (lane & 7);      // row within 16x16 tile
    const int lcol = ((lane >> 4) & 1) * 8;                   // col within 16x16 tile
    const uint32_t xl  = sb + SO_XN + ((trow0 + lrow) * XN_LD + lcol) * 2;
    const uint32_t w1l = sb + SO_W1 + (lrow * W_LD + lcol) * 2;
    const uint32_t w2l = sb + SO_W2 + (lrow * W_LD + lcol) * 2;

    // ---------------- persistent tile loop (256 rows per tile) ----------------
    for (int t = blockIdx.x; t < ntiles; t += gridDim.x) {
        const long long row0 = (long long)t * TROWS;

        __syncthreads();   // previous tile's xstage readers are done

        // ---- coalesced float4 stage of x tile (256x25 f32 = 25600B) ----
        {
            const float4* xg = (const float4*)(x + row0 * DIN);
            float4* d = (float4*)xst;
            #pragma unroll
            for (int i = tid; i < TROWS * DIN / 4; i += NT) d[i] = xg[i];
        }
        __syncthreads();

        // ---- prefetch next tile's x to L2 (hidden under GEMMs) ----
        {
            int tn = t + gridDim.x;
            if (tn < ntiles) {
                const char* pf = (const char*)(x + ((long long)tn * TROWS + tid) * DIN);
                pfL2(pf); pfL2(pf + 96);
            }
        }

        // ---- LayerNorm: thread tid -> row tid (stride-25 smem: conflict-free) ----
        {
            const float* xr = xst + tid * DIN;
            float v[DIN];
            float s = 0.0f, s2 = 0.0f;
            #pragma unroll
            for (int i = 0; i < DIN; i++) { v[i] = xr[i]; s += v[i]; s2 += v[i] * v[i]; }
            float mu = s * (1.0f / DIN);
            float rs = rsqrtf(s2 * (1.0f / DIN) - mu * mu + 1e-5f);
            __half* xo = xns + tid * XN_LD;
            #pragma unroll
            for (int i = 0; i < DIN; i++)
                xo[i] = __float2half_rn((v[i] - mu) * rs * gs[i] + bts[i]);
            #pragma unroll
            for (int i = DIN; i < 32; i++) xo[i] = __half(0.0f);
        }
        __syncwarp();   // warp w's xn rows (32w..32w+31) written by warp w's own threads

        // ================= GEMM1 + GELU -> register A2 fragments ============
        uint32_t afr[2][2][4];
        #pragma unroll
        for (int mt = 0; mt < 2; mt++)
            #pragma unroll
            for (int kk = 0; kk < 2; kk++)
                ldsm4(afr[mt][kk], xl + (16 * mt * XN_LD + 16 * kk) * 2);

        uint32_t a2[2][8][4];
        #pragma unroll
        for (int nt = 0; nt < 8; nt++) {
            uint32_t b[2][4];
            ldsm4t(b[0], w1l + (16 * nt) * 2);
            ldsm4t(b[1], w1l + (16 * W_LD + 16 * nt) * 2);
            float2 bv0 = *(const float2*)&b1s[16 * nt + 2 * tc];
            float2 bv1 = *(const float2*)&b1s[16 * nt + 8 + 2 * tc];
            #pragma unroll
            for (int mt = 0; mt < 2; mt++) {
                float c0[4] = {bv0.x, bv0.y, bv0.x, bv0.y};
                float c1[4] = {bv1.x, bv1.y, bv1.x, bv1.y};
                #pragma unroll
                for (int kk = 0; kk < 2; kk++) {
                    mma16816(c0, afr[mt][kk], b[kk][0], b[kk][1]);
                    mma16816(c1, afr[mt][kk], b[kk][2], b[kk][3]);
                }
                a2[mt][nt][0] = packh2(gelu(c0[0]), gelu(c0[1]));
                a2[mt][nt][1] = packh2(gelu(c0[2]), gelu(c0[3]));
                a2[mt][nt][2] = packh2(gelu(c1[0]), gelu(c1[1]));
                a2[mt][nt][3] = packh2(gelu(c1[2]), gelu(c1[3]));
            }
        }

        // ================= GEMM2 in four n-quarters (regs <= 128) ===========
        #pragma unroll
        for (int nq = 0; nq < 4; nq++) {
            float c2[2][4][4];
            #pragma unroll
            for (int mt = 0; mt < 2; mt++)
                #pragma unroll
                for (int j = 0; j < 4; j++) {                 // acc init = b2
                    float2 bv = *(const float2*)&b2s[32 * nq + 8 * j + 2 * tc];
                    c2[mt][j][0] = bv.x; c2[mt][j][1] = bv.y;
                    c2[mt][j][2] = bv.x; c2[mt][j][3] = bv.y;
                }
            #pragma unroll
            for (int ks = 0; ks < 8; ks++) {
                #pragma unroll
                for (int nt = 0; nt < 2; nt++) {
                    uint32_t b[4];
                    ldsm4t(b, w2l + (16 * ks * W_LD + 32 * nq + 16 * nt) * 2);
                    #pragma unroll
                    for (int mt = 0; mt < 2; mt++) {
                        mma16816(c2[mt][2 * nt],     a2[mt][ks], b[0], b[1]);
                        mma16816(c2[mt][2 * nt + 1], a2[mt][ks], b[2], b[3]);
                    }
                }
            }
            // epilogue: direct coalesced-by-warp float2 stores
            #pragma unroll
            for (int mt = 0; mt < 2; mt++) {
                long long r = row0 + trow0 + 16 * mt + g;
                #pragma unroll
                for (int j = 0; j < 4; j++) {
                    int col = 32 * nq + 8 * j + 2 * tc;
                    *(float2*)(out + r * DP + col)       = make_float2(c2[mt][j][0], c2[mt][j][1]);
                    *(float2*)(out + (r + 8) * DP + col) = make_float2(c2[mt][j][2], c2[mt][j][3]);
                }
            }
        }
    }
}

extern "C" void kernel_launch(void* const* d_in, const int* in_sizes, int n_in,
                              void* d_out, int out_size)
{
    const float* x     = (const float*)d_in[0];
    const float* gamma = (const float*)d_in[1];
    const float* beta  = (const float*)d_in[2];
    const float* w1    = (const float*)d_in[3];
    const float* b1    = (const float*)d_in[4];
    const float* w2    = (const float*)d_in[5];
    const float* b2    = (const float*)d_in[6];
    float* out = (float*)d_out;

    static int n_sm = 0;   // one-time query + attribute set (not a work guard)
    if (n_sm == 0) {
        cudaDeviceProp prop;
        cudaGetDeviceProperties(&prop, 0);
        n_sm = prop.multiProcessorCount;
        cudaFuncSetAttribute(ip_mma_kernel,
                             cudaFuncAttributeMaxDynamicSharedMemorySize,
                             SMEM_BYTES);
    }

    const int rows = in_sizes[0] / DIN;   // 524288
    const int ntiles = rows / TROWS;      // 2048
    const int grid = n_sm * 2;            // persistent: 2 CTAs/SM
    ip_mma_kernel<<<grid, NT, SMEM_BYTES>>>(x, gamma, beta, w1, b1, w2, b2, out, ntiles);
}

// round 10
// speedup vs baseline: 7.8283x; 1.3192x over previous
#include <cuda_runtime.h>
#include <cuda_fp16.h>
#include <cstdint>

#define DIN   25
#define DP    128
#define NT    256        // 8 warps; warp w owns rows 32w..32w+31 of a 256-row tile
#define TROWS 256        // rows per CTA tile
#define W_LD  136        // halves per weight row (272B, conflict-free under ldmatrix)
#define XN_LD 40         // halves per xn row (80B)

// shared byte offsets (16B aligned)
#define SO_W1  0         // 32x136 half   = 8704
#define SO_W2  8704      // 128x136 half  = 34816
#define SO_XN  43520     // 256x40 half   = 20480
#define SO_XS  64000     // 256x25 f32    = 25600
#define SO_B1  89600     // 512
#define SO_B2  90112     // 512
#define SO_G   90624     // 128
#define SO_BT  90752     // 128
#define SMEM_BYTES 90880 // x2 CTAs = 177.5KB/SM (<= 228KB)

__device__ __forceinline__ uint32_t s2u(const void* p) {
    uint32_t a;
    asm("{ .reg .u64 t; cvta.to.shared.u64 t, %1; cvt.u32.u64 %0, t; }" : "=r"(a) : "l"(p));
    return a;
}
__device__ __forceinline__ void ldsm4(uint32_t* r, uint32_t addr) {
    asm volatile("ldmatrix.sync.aligned.m8n8.x4.shared.b16 {%0,%1,%2,%3}, [%4];"
                 : "=r"(r[0]), "=r"(r[1]), "=r"(r[2]), "=r"(r[3]) : "r"(addr));
}
__device__ __forceinline__ void ldsm4t(uint32_t* r, uint32_t addr) {
    asm volatile("ldmatrix.sync.aligned.m8n8.x4.trans.shared.b16 {%0,%1,%2,%3}, [%4];"
                 : "=r"(r[0]), "=r"(r[1]), "=r"(r[2]), "=r"(r[3]) : "r"(addr));
}
__device__ __forceinline__ void mma16816(float* c, const uint32_t* a, uint32_t b0, uint32_t b1) {
    asm volatile("mma.sync.aligned.m16n8k16.row.col.f32.f16.f16.f32 "
                 "{%0,%1,%2,%3}, {%4,%5,%6,%7}, {%8,%9}, {%0,%1,%2,%3};"
                 : "+f"(c[0]), "+f"(c[1]), "+f"(c[2]), "+f"(c[3])
                 : "r"(a[0]), "r"(a[1]), "r"(a[2]), "r"(a[3]), "r"(b0), "r"(b1));
}
__device__ __forceinline__ uint32_t packh2(float lo, float hi) {
    __half2 h = __floats2half2_rn(lo, hi);
    return *(uint32_t*)&h;
}
// tanh-form GELU via hardware tanh (MUFU.TANH): branch-free, ~6 instr.
// max abs dev from exact-erf GELU ~4e-4 at |v|~3 (5sigma here), <=2e-4 typical.
__device__ __forceinline__ float gelu(float v) {
    float u = 0.7978845608028654f * fmaf(0.044715f * v, v * v, v);
    float t;
    asm("tanh.approx.f32 %0, %1;" : "=f"(t) : "f"(u));
    return 0.5f * v * (1.0f + t);
}
__device__ __forceinline__ void pfL2(const void* p) {
    asm volatile("prefetch.global.L2 [%0];" :: "l"(p));
}

__global__ __launch_bounds__(NT, 2)
void ip_mma_kernel(const float* __restrict__ x,
                   const float* __restrict__ gamma,
                   const float* __restrict__ beta,
                   const float* __restrict__ w1,
                   const float* __restrict__ b1,
                   const float* __restrict__ w2,
                   const float* __restrict__ b2,
                   float* __restrict__ out, int ntiles)
{
    extern __shared__ char smc[];
    const uint32_t sb = s2u(smc);
    __half* w1s = (__half*)(smc + SO_W1);
    __half* w2s = (__half*)(smc + SO_W2);
    __half* xns = (__half*)(smc + SO_XN);
    float*  xst = (float*)(smc + SO_XS);
    float*  b1s = (float*)(smc + SO_B1);
    float*  b2s = (float*)(smc + SO_B2);
    float*  gs  = (float*)(smc + SO_G);
    float*  bts = (float*)(smc + SO_BT);

    const int tid  = threadIdx.x;
    const int warp = tid >> 5;
    const int lane = tid & 31;
    const int g    = lane >> 2;       // row group 0..7
    const int tc   = lane & 3;        // col pair  0..3

    // ---------------- one-time staging ----------------
    for (int i = tid; i < 476; i += NT)                       // zero w1 K-pad rows 25..31
        ((uint32_t*)(smc + SO_W1 + 25 * W_LD * 2))[i] = 0u;
    for (int i = tid; i < DIN * DP; i += NT) {                // w1 [25x128] -> half
        int k = i >> 7, n = i & 127;
        w1s[k * W_LD + n] = __float2half_rn(w1[i]);
    }
    for (int i = tid; i < DP * DP / 4; i += NT) {             // w2 [128x128] -> half
        int k = i >> 5, n4 = i & 31;
        float4 v = ((const float4*)w2)[i];
        __half2 h01 = __floats2half2_rn(v.x, v.y);
        __half2 h23 = __floats2half2_rn(v.z, v.w);
        uint2 u;
        u.x = *(uint32_t*)&h01; u.y = *(uint32_t*)&h23;
        *(uint2*)(w2s + k * W_LD + n4 * 4) = u;
    }
    if (tid < DP) { b1s[tid] = b1[tid]; b2s[tid] = b2[tid]; }
    if (tid < DIN) { gs[tid] = gamma[tid]; bts[tid] = beta[tid]; }

    const int trow0 = warp * 32;
    const int lrow = ((lane >> 3) & 1) * 8 + (lane & 7);      // row within 16x16 tile
    const int lcol = ((lane >> 4) & 1) * 8;                   // col within 16x16 tile
    const uint32_t xl  = sb + SO_XN + ((trow0 + lrow) * XN_LD + lcol) * 2;
    const uint32_t w1l = sb + SO_W1 + (lrow * W_LD + lcol) * 2;
    const uint32_t w2l = sb + SO_W2 + (lrow * W_LD + lcol) * 2;

    // ---------------- persistent tile loop (256 rows per tile) ----------------
    for (int t = blockIdx.x; t < ntiles; t += gridDim.x) {
        const long long row0 = (long long)t * TROWS;

        __syncthreads();   // previous tile's xstage readers are done

        // ---- coalesced float4 stage of x tile (256x25 f32 = 25600B) ----
        {
            const float4* xg = (const float4*)(x + row0 * DIN);
            float4* d = (float4*)xst;
            #pragma unroll
            for (int i = tid; i < TROWS * DIN / 4; i += NT) d[i] = xg[i];
        }
        __syncthreads();

        // ---- prefetch next tile's x to L2 (hidden under GEMMs) ----
        {
            int tn = t + gridDim.x;
            if (tn < ntiles) {
                const char* pf = (const char*)(x + ((long long)tn * TROWS + tid) * DIN);
                pfL2(pf); pfL2(pf + 96);
            }
        }

        // ---- LayerNorm: thread tid -> row tid (stride-25 smem: conflict-free) ----
        {
            const float* xr = xst + tid * DIN;
            float v[DIN];
            float s = 0.0f, s2 = 0.0f;
            #pragma unroll
            for (int i = 0; i < DIN; i++) { v[i] = xr[i]; s += v[i]; s2 += v[i] * v[i]; }
            float mu = s * (1.0f / DIN);
            float rs = rsqrtf(s2 * (1.0f / DIN) - mu * mu + 1e-5f);
            __half* xo = xns + tid * XN_LD;
            #pragma unroll
            for (int i = 0; i < DIN; i++)
                xo[i] = __float2half_rn((v[i] - mu) * rs * gs[i] + bts[i]);
            #pragma unroll
            for (int i = DIN; i < 32; i++) xo[i] = __half(0.0f);
        }
        __syncwarp();   // warp w's xn rows (32w..32w+31) written by warp w's own threads

        // ================= GEMM1 + GELU -> register A2 fragments ============
        uint32_t afr[2][2][4];
        #pragma unroll
        for (int mt = 0; mt < 2; mt++)
            #pragma unroll
            for (int kk = 0; kk < 2; kk++)
                ldsm4(afr[mt][kk], xl + (16 * mt * XN_LD + 16 * kk) * 2);

        uint32_t a2[2][8][4];
        #pragma unroll
        for (int nt = 0; nt < 8; nt++) {
            uint32_t b[2][4];
            ldsm4t(b[0], w1l + (16 * nt) * 2);
            ldsm4t(b[1], w1l + (16 * W_LD + 16 * nt) * 2);
            float2 bv0 = *(const float2*)&b1s[16 * nt + 2 * tc];
            float2 bv1 = *(const float2*)&b1s[16 * nt + 8 + 2 * tc];
            #pragma unroll
            for (int mt = 0; mt < 2; mt++) {
                float c0[4] = {bv0.x, bv0.y, bv0.x, bv0.y};
                float c1[4] = {bv1.x, bv1.y, bv1.x, bv1.y};
                #pragma unroll
                for (int kk = 0; kk < 2; kk++) {
                    mma16816(c0, afr[mt][kk], b[kk][0], b[kk][1]);
                    mma16816(c1, afr[mt][kk], b[kk][2], b[kk][3]);
                }
                a2[mt][nt][0] = packh2(gelu(c0[0]), gelu(c0[1]));
                a2[mt][nt][1] = packh2(gelu(c0[2]), gelu(c0[3]));
                a2[mt][nt][2] = packh2(gelu(c1[0]), gelu(c1[1]));
                a2[mt][nt][3] = packh2(gelu(c1[2]), gelu(c1[3]));
            }
        }

        // ================= GEMM2 in four n-quarters (regs <= 128) ===========
        #pragma unroll
        for (int nq = 0; nq < 4; nq++) {
            float c2[2][4][4];
            #pragma unroll
            for (int mt = 0; mt < 2; mt++)
                #pragma unroll
                for (int j = 0; j < 4; j++) {                 // acc init = b2
                    float2 bv = *(const float2*)&b2s[32 * nq + 8 * j + 2 * tc];
                    c2[mt][j][0] = bv.x; c2[mt][j][1] = bv.y;
                    c2[mt][j][2] = bv.x; c2[mt][j][3] = bv.y;
                }
            #pragma unroll
            for (int ks = 0; ks < 8; ks++) {
                #pragma unroll
                for (int nt = 0; nt < 2; nt++) {
                    uint32_t b[4];
                    ldsm4t(b, w2l + (16 * ks * W_LD + 32 * nq + 16 * nt) * 2);
                    #pragma unroll
                    for (int mt = 0; mt < 2; mt++) {
                        mma16816(c2[mt][2 * nt],     a2[mt][ks], b[0], b[1]);
                        mma16816(c2[mt][2 * nt + 1], a2[mt][ks], b[2], b[3]);
                    }
                }
            }
            // epilogue: direct coalesced-by-warp float2 stores
            #pragma unroll
            for (int mt = 0; mt < 2; mt++) {
                long long r = row0 + trow0 + 16 * mt + g;
                #pragma unroll
                for (int j = 0; j < 4; j++) {
                    int col = 32 * nq + 8 * j + 2 * tc;
                    *(float2*)(out + r * DP + col)       = make_float2(c2[mt][j][0], c2[mt][j][1]);
                    *(float2*)(out + (r + 8) * DP + col) = make_float2(c2[mt][j][2], c2[mt][j][3]);
                }
            }
        }
    }
}

extern "C" void kernel_launch(void* const* d_in, const int* in_sizes, int n_in,
                              void* d_out, int out_size)
{
    const float* x     = (const float*)d_in[0];
    const float* gamma = (const float*)d_in[1];
    const float* beta  = (const float*)d_in[2];
    const float* w1    = (const float*)d_in[3];
    const float* b1    = (const float*)d_in[4];
    const float* w2    = (const float*)d_in[5];
    const float* b2    = (const float*)d_in[6];
    float* out = (float*)d_out;

    static int n_sm = 0;   // one-time query + attribute set (not a work guard)
    if (n_sm == 0) {
        cudaDeviceProp prop;
        cudaGetDeviceProperties(&prop, 0);
        n_sm = prop.multiProcessorCount;
        cudaFuncSetAttribute(ip_mma_kernel,
                             cudaFuncAttributeMaxDynamicSharedMemorySize,
                             SMEM_BYTES);
    }

    const int rows = in_sizes[0] / DIN;   // 524288
    const int ntiles = rows / TROWS;      // 2048
    const int grid = n_sm * 2;            // persistent: 2 CTAs/SM
    ip_mma_kernel<<<grid, NT, SMEM_BYTES>>>(x, gamma, beta, w1, b1, w2, b2, out, ntiles);
}

// round 11
// speedup vs baseline: 7.9873x; 1.0203x over previous
#include <cuda_runtime.h>
#include <cuda_fp16.h>
#include <cstdint>

#define DIN   25
#define DP    128
#define NT    256        // 8 warps; warp w owns rows 32w..32w+31 of a 256-row tile
#define TROWS 256        // rows per CTA tile
#define W_LD  136        // halves per weight row (272B, conflict-free under ldmatrix)
#define XN_LD 40         // halves per xn row (80B)

// shared byte offsets (16B aligned)
#define SO_W1  0         // 32x136 half   = 8704
#define SO_W2  8704      // 128x136 half  = 34816
#define SO_XN  43520     // 256x40 half   = 20480
#define SO_XS  64000     // 256x25 f32    = 25600
#define SO_B1  89600     // 512
#define SO_B2  90112     // 512
#define SO_G   90624     // 128
#define SO_BT  90752     // 128
#define SMEM_BYTES 90880 // x2 CTAs = 177.5KB/SM (<= 228KB)

__device__ __forceinline__ uint32_t s2u(const void* p) {
    uint32_t a;
    asm("{ .reg .u64 t; cvta.to.shared.u64 t, %1; cvt.u32.u64 %0, t; }" : "=r"(a) : "l"(p));
    return a;
}
__device__ __forceinline__ void ldsm4(uint32_t* r, uint32_t addr) {
    asm volatile("ldmatrix.sync.aligned.m8n8.x4.shared.b16 {%0,%1,%2,%3}, [%4];"
                 : "=r"(r[0]), "=r"(r[1]), "=r"(r[2]), "=r"(r[3]) : "r"(addr));
}
__device__ __forceinline__ void ldsm4t(uint32_t* r, uint32_t addr) {
    asm volatile("ldmatrix.sync.aligned.m8n8.x4.trans.shared.b16 {%0,%1,%2,%3}, [%4];"
                 : "=r"(r[0]), "=r"(r[1]), "=r"(r[2]), "=r"(r[3]) : "r"(addr));
}
__device__ __forceinline__ void mma16816(float* c, const uint32_t* a, uint32_t b0, uint32_t b1) {
    asm volatile("mma.sync.aligned.m16n8k16.row.col.f32.f16.f16.f32 "
                 "{%0,%1,%2,%3}, {%4,%5,%6,%7}, {%8,%9}, {%0,%1,%2,%3};"
                 : "+f"(c[0]), "+f"(c[1]), "+f"(c[2]), "+f"(c[3])
                 : "r"(a[0]), "r"(a[1]), "r"(a[2]), "r"(a[3]), "r"(b0), "r"(b1));
}
__device__ __forceinline__ uint32_t packh2(float lo, float hi) {
    __half2 h = __floats2half2_rn(lo, hi);
    return *(uint32_t*)&h;
}
// tanh-form GELU via hardware tanh (MUFU.TANH): branch-free.
__device__ __forceinline__ float gelu(float v) {
    float u = 0.7978845608028654f * fmaf(0.044715f * v, v * v, v);
    float t;
    asm("tanh.approx.f32 %0, %1;" : "=f"(t) : "f"(u));
    return 0.5f * v * (1.0f + t);
}
__device__ __forceinline__ void cpa16(uint32_t saddr, const void* g) {
    asm volatile("cp.async.ca.shared.global [%0], [%1], 16;" :: "r"(saddr), "l"(g));
}
__device__ __forceinline__ void cpa_wait_all() {
    asm volatile("cp.async.wait_all;" ::: "memory");
}

__global__ __launch_bounds__(NT, 2)
void ip_mma_kernel(const float* __restrict__ x,
                   const float* __restrict__ gamma,
                   const float* __restrict__ beta,
                   const float* __restrict__ w1,
                   const float* __restrict__ b1,
                   const float* __restrict__ w2,
                   const float* __restrict__ b2,
                   float* __restrict__ out, int ntiles)
{
    extern __shared__ char smc[];
    const uint32_t sb = s2u(smc);
    __half* w1s = (__half*)(smc + SO_W1);
    __half* w2s = (__half*)(smc + SO_W2);
    float*  xst = (float*)(smc + SO_XS);
    float*  b1s = (float*)(smc + SO_B1);
    float*  b2s = (float*)(smc + SO_B2);
    float*  gs  = (float*)(smc + SO_G);
    float*  bts = (float*)(smc + SO_BT);

    const int tid  = threadIdx.x;
    const int warp = tid >> 5;
    const int lane = tid & 31;
    const int g    = lane >> 2;       // row group 0..7
    const int tc   = lane & 3;        // col pair  0..3

    // ---- async stage of FIRST x tile (overlaps weight staging) ----
    {
        const char* xg = (const char*)(x + (long long)blockIdx.x * TROWS * DIN);
        const uint32_t sdst = sb + SO_XS;
        for (int i = tid; i < TROWS * DIN / 4; i += NT)
            cpa16(sdst + i * 16, xg + i * 16);
    }

    // ---------------- one-time weight staging ----------------
    for (int i = tid; i < 476; i += NT)                       // zero w1 K-pad rows 25..31
        ((uint32_t*)(smc + SO_W1 + 25 * W_LD * 2))[i] = 0u;
    for (int i = tid; i < DIN * DP; i += NT) {                // w1 [25x128] -> half
        int k = i >> 7, n = i & 127;
        w1s[k * W_LD + n] = __float2half_rn(w1[i]);
    }
    for (int i = tid; i < DP * DP / 4; i += NT) {             // w2 [128x128] -> half
        int k = i >> 5, n4 = i & 31;
        float4 v = ((const float4*)w2)[i];
        __half2 h01 = __floats2half2_rn(v.x, v.y);
        __half2 h23 = __floats2half2_rn(v.z, v.w);
        uint2 u;
        u.x = *(uint32_t*)&h01; u.y = *(uint32_t*)&h23;
        *(uint2*)(w2s + k * W_LD + n4 * 4) = u;
    }
    if (tid < DP) { b1s[tid] = b1[tid]; b2s[tid] = b2[tid]; }
    if (tid < DIN) { gs[tid] = gamma[tid]; bts[tid] = beta[tid]; }

    const int trow0 = warp * 32;
    const int lrow = ((lane >> 3) & 1) * 8 + (lane & 7);      // row within 16x16 tile
    const int lcol = ((lane >> 4) & 1) * 8;                   // col within 16x16 tile
    const uint32_t xl  = sb + SO_XN + ((trow0 + lrow) * XN_LD + lcol) * 2;
    const uint32_t w1l = sb + SO_W1 + (lrow * W_LD + lcol) * 2;
    const uint32_t w2l = sb + SO_W2 + (lrow * W_LD + lcol) * 2;

    // ---------------- persistent tile loop (256 rows per tile) ----------------
    for (int t = blockIdx.x; t < ntiles; t += gridDim.x) {
        const long long row0 = (long long)t * TROWS;

        cpa_wait_all();     // this thread's stage copies for tile t are done
        __syncthreads();    // ... and every thread's (stage of t fully visible)

        // ---- LayerNorm: thread tid -> row tid (stride-25 smem: conflict-free) ----
        {
            const float* xr = xst + tid * DIN;
            float v[DIN];
            float s = 0.0f, s2 = 0.0f;
            #pragma unroll
            for (int i = 0; i < DIN; i++) { v[i] = xr[i]; s += v[i]; s2 += v[i] * v[i]; }
            float mu = s * (1.0f / DIN);
            float rs = rsqrtf(s2 * (1.0f / DIN) - mu * mu + 1e-5f);
            uint32_t u[16];
            #pragma unroll
            for (int i = 0; i < 12; i++)
                u[i] = packh2((v[2*i] - mu) * rs * gs[2*i] + bts[2*i],
                              (v[2*i+1] - mu) * rs * gs[2*i+1] + bts[2*i+1]);
            u[12] = packh2((v[24] - mu) * rs * gs[24] + bts[24], 0.0f);
            u[13] = 0u; u[14] = 0u; u[15] = 0u;
            uint32_t xo = sb + SO_XN + tid * (XN_LD * 2);     // 80B rows, 16B aligned
            #pragma unroll
            for (int q = 0; q < 4; q++)
                asm volatile("st.shared.v4.b32 [%0], {%1,%2,%3,%4};"
                             :: "r"(xo + q * 16),
                                "r"(u[4*q]), "r"(u[4*q+1]), "r"(u[4*q+2]), "r"(u[4*q+3]));
        }
        __syncthreads();    // all LN reads of xst done; xn visible CTA-wide

        // ---- fire-and-forget stage of NEXT tile (completes under the GEMMs) ----
        {
            int tn = t + gridDim.x;
            if (tn < ntiles) {
                const char* xg = (const char*)(x + (long long)tn * TROWS * DIN);
                const uint32_t sdst = sb + SO_XS;
                for (int i = tid; i < TROWS * DIN / 4; i += NT)
                    cpa16(sdst + i * 16, xg + i * 16);
            }
        }

        // ================= GEMM1 + GELU -> register A2 fragments ============
        uint32_t afr[2][2][4];
        #pragma unroll
        for (int mt = 0; mt < 2; mt++)
            #pragma unroll
            for (int kk = 0; kk < 2; kk++)
                ldsm4(afr[mt][kk], xl + (16 * mt * XN_LD + 16 * kk) * 2);

        uint32_t a2[2][8][4];
        #pragma unroll
        for (int nt = 0; nt < 8; nt++) {
            uint32_t b[2][4];
            ldsm4t(b[0], w1l + (16 * nt) * 2);
            ldsm4t(b[1], w1l + (16 * W_LD + 16 * nt) * 2);
            float2 bv0 = *(const float2*)&b1s[16 * nt + 2 * tc];
            float2 bv1 = *(const float2*)&b1s[16 * nt + 8 + 2 * tc];
            #pragma unroll
            for (int mt = 0; mt < 2; mt++) {
                float c0[4] = {bv0.x, bv0.y, bv0.x, bv0.y};
                float c1[4] = {bv1.x, bv1.y, bv1.x, bv1.y};
                #pragma unroll
                for (int kk = 0; kk < 2; kk++) {
                    mma16816(c0, afr[mt][kk], b[kk][0], b[kk][1]);
                    mma16816(c1, afr[mt][kk], b[kk][2], b[kk][3]);
                }
                a2[mt][nt][0] = packh2(gelu(c0[0]), gelu(c0[1]));
                a2[mt][nt][1] = packh2(gelu(c0[2]), gelu(c0[3]));
                a2[mt][nt][2] = packh2(gelu(c1[0]), gelu(c1[1]));
                a2[mt][nt][3] = packh2(gelu(c1[2]), gelu(c1[3]));
            }
        }

        // ================= GEMM2 in four n-quarters (regs <= 128) ===========
        #pragma unroll
        for (int nq = 0; nq < 4; nq++) {
            float c2[2][4][4];
            #pragma unroll
            for (int mt = 0; mt < 2; mt++)
                #pragma unroll
                for (int j = 0; j < 4; j++) {                 // acc init = b2
                    float2 bv = *(const float2*)&b2s[32 * nq + 8 * j + 2 * tc];
                    c2[mt][j][0] = bv.x; c2[mt][j][1] = bv.y;
                    c2[mt][j][2] = bv.x; c2[mt][j][3] = bv.y;
                }
            #pragma unroll
            for (int ks = 0; ks < 8; ks++) {
                #pragma unroll
                for (int nt = 0; nt < 2; nt++) {
                    uint32_t b[4];
                    ldsm4t(b, w2l + (16 * ks * W_LD + 32 * nq + 16 * nt) * 2);
                    #pragma unroll
                    for (int mt = 0; mt < 2; mt++) {
                        mma16816(c2[mt][2 * nt],     a2[mt][ks], b[0], b[1]);
                        mma16816(c2[mt][2 * nt + 1], a2[mt][ks], b[2], b[3]);
                    }
                }
            }
            // epilogue: direct coalesced-by-warp float2 stores
            #pragma unroll
            for (int mt = 0; mt < 2; mt++) {
                long long r = row0 + trow0 + 16 * mt + g;
                #pragma unroll
                for (int j = 0; j < 4; j++) {
                    int col = 32 * nq + 8 * j + 2 * tc;
                    *(float2*)(out + r * DP + col)       = make_float2(c2[mt][j][0], c2[mt][j][1]);
                    *(float2*)(out + (r + 8) * DP + col) = make_float2(c2[mt][j][2], c2[mt][j][3]);
                }
            }
        }
    }
}

extern "C" void kernel_launch(void* const* d_in, const int* in_sizes, int n_in,
                              void* d_out, int out_size)
{
    const float* x     = (const float*)d_in[0];
    const float* gamma = (const float*)d_in[1];
    const float* beta  = (const float*)d_in[2];
    const float* w1    = (const float*)d_in[3];
    const float* b1    = (const float*)d_in[4];
    const float* w2    = (const float*)d_in[5];
    const float* b2    = (const float*)d_in[6];
    float* out = (float*)d_out;

    static int n_sm = 0;   // one-time query + attribute set (not a work guard)
    if (n_sm == 0) {
        cudaDeviceProp prop;
        cudaGetDeviceProperties(&prop, 0);
        n_sm = prop.multiProcessorCount;
        cudaFuncSetAttribute(ip_mma_kernel,
                             cudaFuncAttributeMaxDynamicSharedMemorySize,
                             SMEM_BYTES);
    }

    const int rows = in_sizes[0] / DIN;   // 524288
    const int ntiles = rows / TROWS;      // 2048
    const int grid = n_sm * 2;            // persistent: 2 CTAs/SM
    ip_mma_kernel<<<grid, NT, SMEM_BYTES>>>(x, gamma, beta, w1, b1, w2, b2, out, ntiles);
}